// round 4
// baseline (speedup 1.0000x reference)
#include <cuda_runtime.h>
#include <cuda_bf16.h>

#define EMBED 100
#define BATCH 8192
#define FUNC_VOCAB 10000
#define VEC4_PER_MAT 2500   // 100*100/4
#define F4_PER_ROW   25     // 100/4
#define NTHREADS     256
#define ITERS        10     // ceil(2500/256)

#define SORT_CTAS    32
#define SORT_THREADS 256
#define BINS_PER_THR 40     // 256*40 = 10240 >= 10000

__device__ int g_perm[BATCH];
__device__ int g_hist[FUNC_VOCAB];   // zero at load; re-zeroed each launch in phase 3
__device__ int g_offs[FUNC_VOCAB];   // fully overwritten by scan each launch
__device__ unsigned long long g_c1;  // monotonic arrival counter (phase-1 barrier)
__device__ unsigned long long g_c2;  // monotonic release counter (scan-done)

// ---------------------------------------------------------------------------
// Multi-CTA counting sort by functor id, single kernel, spin-barrier phased.
// 32 CTAs x 256 thr = 8192 threads, 1 batch element each.
// Counters are monotonic: launch L sees c1 in [32L, 32L+32), releases at c2>L.
// ---------------------------------------------------------------------------
__global__ __launch_bounds__(SORT_THREADS)
void sort_by_functor_kernel(const int* __restrict__ Xf)
{
    const int t   = threadIdx.x;
    const int b   = blockIdx.x * SORT_THREADS + t;
    const int f   = Xf[b];

    __shared__ int s_last;                 // 1 if this CTA arrived last
    __shared__ unsigned long long s_L;     // launch epoch
    __shared__ int s_sums[SORT_THREADS / 32];

    // Phase 1: global histogram (no-return reduce -> REDG)
    atomicAdd(&g_hist[f], 1);
    __syncthreads();

    if (t == 0) {
        __threadfence();
        unsigned long long a = atomicAdd(&g_c1, 1ULL);
        unsigned long long L = a / SORT_CTAS;
        s_L = L;
        s_last = ((a % SORT_CTAS) == SORT_CTAS - 1) ? 1 : 0;
    }
    __syncthreads();

    // Phase 2: last-arriving CTA scans the histogram into exclusive offsets
    if (s_last) {
        const int base = t * BINS_PER_THR;
        int cnt[BINS_PER_THR];
        int local = 0;
        #pragma unroll
        for (int i = 0; i < BINS_PER_THR; i++) {
            int idx = base + i;
            int v = (idx < FUNC_VOCAB) ? g_hist[idx] : 0;
            cnt[i] = local;
            local += v;
        }
        // block exclusive scan of per-thread sums
        const int lane = t & 31, wid = t >> 5;
        int x = local;
        #pragma unroll
        for (int o = 1; o < 32; o <<= 1) {
            int y = __shfl_up_sync(0xFFFFFFFFu, x, o);
            if (lane >= o) x += y;
        }
        if (lane == 31) s_sums[wid] = x;
        __syncthreads();
        if (wid == 0 && lane < (SORT_THREADS / 32)) {
            int w = s_sums[lane];
            #pragma unroll
            for (int o = 1; o < (SORT_THREADS / 32); o <<= 1) {
                int y = __shfl_up_sync(0xFFu, w, o);
                if (lane >= o) w += y;
            }
            s_sums[lane] = w;
        }
        __syncthreads();
        const int excl = (x - local) + (wid > 0 ? s_sums[wid - 1] : 0);
        #pragma unroll
        for (int i = 0; i < BINS_PER_THR; i++) {
            int idx = base + i;
            if (idx < FUNC_VOCAB) g_offs[idx] = excl + cnt[i];
        }
        __syncthreads();
        if (t == 0) {
            __threadfence();
            atomicAdd(&g_c2, 1ULL);
        }
    } else if (t == 0) {
        // spin until scan of this launch is published
        while (atomicAdd(&g_c2, 0ULL) <= s_L) { __nanosleep(64); }
    }
    __syncthreads();

    // Phase 3: scatter + re-zero histogram for the next launch
    {
        int pos = atomicAdd(&g_offs[f], 1);
        g_perm[pos] = b;
    }
    const int gtid = blockIdx.x * SORT_THREADS + t;
    for (int i = gtid; i < FUNC_VOCAB; i += SORT_CTAS * SORT_THREADS)
        g_hist[i] = 0;
}

// ---------------------------------------------------------------------------
// out[b] = ctx[b]^T * M[f[b]] * arg[b]
// ---------------------------------------------------------------------------
__global__ __launch_bounds__(NTHREADS)
void matrix_skipgram_kernel(const int* __restrict__ X_argument,
                            const int* __restrict__ X_functor,
                            const int* __restrict__ X_context,
                            const float* __restrict__ noun_matrix,
                            const float* __restrict__ functor_table,
                            const float* __restrict__ context_table,
                            float* __restrict__ out)
{
    const int b = g_perm[blockIdx.x];
    const int t = threadIdx.x;

    __shared__ float s_arg[EMBED];
    __shared__ float s_ctx[EMBED];
    __shared__ float s_red[NTHREADS / 32];

    {
        const float* av = noun_matrix   + (size_t)X_argument[b] * EMBED;
        const float* cv = context_table + (size_t)X_context[b]  * EMBED;
        if (t < EMBED) {
            s_arg[t] = av[t];
            s_ctx[t] = cv[t];
        }
    }

    const float4* __restrict__ M =
        reinterpret_cast<const float4*>(functor_table + (size_t)X_functor[b] * (EMBED * EMBED));

    // Front-batch ALL matrix loads: 10 independent LDG.128 per thread in flight.
    float4 m[ITERS];
    #pragma unroll
    for (int it = 0; it < ITERS; ++it) {
        const int k = t + it * NTHREADS;
        if (k < VEC4_PER_MAT) m[it] = __ldg(&M[k]);
    }

    __syncthreads();   // s_arg/s_ctx ready (overlapped with load latency above)

    float acc = 0.0f;
    #pragma unroll
    for (int it = 0; it < ITERS; ++it) {
        const int k = t + it * NTHREADS;
        if (k < VEC4_PER_MAT) {
            const int i  = k / F4_PER_ROW;
            const int j4 = (k - i * F4_PER_ROW) * 4;
            float dot = m[it].x * s_arg[j4]
                      + m[it].y * s_arg[j4 + 1]
                      + m[it].z * s_arg[j4 + 2]
                      + m[it].w * s_arg[j4 + 3];
            acc = fmaf(s_ctx[i], dot, acc);
        }
    }

    #pragma unroll
    for (int o = 16; o > 0; o >>= 1)
        acc += __shfl_xor_sync(0xFFFFFFFFu, acc, o);

    if ((t & 31) == 0)
        s_red[t >> 5] = acc;
    __syncthreads();

    if (t < (NTHREADS / 32)) {
        acc = s_red[t];
        #pragma unroll
        for (int o = (NTHREADS / 64); o > 0; o >>= 1)
            acc += __shfl_xor_sync(0xFFu, acc, o);
        if (t == 0)
            out[b] = acc;
    }
}

extern "C" void kernel_launch(void* const* d_in, const int* in_sizes, int n_in,
                              void* d_out, int out_size)
{
    const int*   X_argument    = (const int*)  d_in[0];
    const int*   X_functor     = (const int*)  d_in[1];
    const int*   X_context     = (const int*)  d_in[2];
    const float* noun_matrix   = (const float*)d_in[3];
    const float* functor_table = (const float*)d_in[4];
    const float* context_table = (const float*)d_in[5];
    float* out = (float*)d_out;

    sort_by_functor_kernel<<<SORT_CTAS, SORT_THREADS>>>(X_functor);
    matrix_skipgram_kernel<<<BATCH, NTHREADS>>>(
        X_argument, X_functor, X_context,
        noun_matrix, functor_table, context_table, out);
}

// round 6
// speedup vs baseline: 1.2755x; 1.2755x over previous
#include <cuda_runtime.h>
#include <cuda_bf16.h>

#define EMBED 100
#define BATCH 8192
#define VEC4_PER_MAT 2500   // 100*100/4
#define F4_PER_ROW   25     // 100/4
#define NTHREADS     256
#define ITERS        10     // ceil(2500/256); iters 0..8 always in-bounds

__global__ __launch_bounds__(NTHREADS)
void matrix_skipgram_kernel(const int* __restrict__ X_argument,
                            const int* __restrict__ X_functor,
                            const int* __restrict__ X_context,
                            const float* __restrict__ noun_matrix,
                            const float* __restrict__ functor_table,
                            const float* __restrict__ context_table,
                            float* __restrict__ out)
{
    const int b = blockIdx.x;
    const int t = threadIdx.x;

    __shared__ float s_arg[EMBED];
    __shared__ float s_ctx[EMBED];
    __shared__ float s_red[NTHREADS / 32];

    // Stage vectors (first 4 warps) — these LDGs issue first.
    {
        const float* av = noun_matrix   + (size_t)X_argument[b] * EMBED;
        const float* cv = context_table + (size_t)X_context[b]  * EMBED;
        if (t < EMBED) {
            s_arg[t] = av[t];
            s_ctx[t] = cv[t];
        }
    }

    const float4* __restrict__ M =
        reinterpret_cast<const float4*>(functor_table + (size_t)X_functor[b] * (EMBED * EMBED));

    // UNCONDITIONAL front-batched loads: 10 independent LDG.128 per thread.
    // Iters 0..8: k = t + it*256 <= 255 + 2048 = 2303 < 2500, always valid.
    // Iter 9: clamp OOB address to 0; its contribution is zeroed below.
    const int k9      = t + 9 * NTHREADS;
    const bool v9     = (k9 < VEC4_PER_MAT);
    float4 m[ITERS];
    #pragma unroll
    for (int it = 0; it < ITERS - 1; ++it)
        m[it] = __ldg(&M[t + it * NTHREADS]);
    m[ITERS - 1] = __ldg(&M[v9 ? k9 : 0]);

    __syncthreads();   // s_arg/s_ctx ready; matrix loads already in flight

    float acc = 0.0f;
    #pragma unroll
    for (int it = 0; it < ITERS - 1; ++it) {
        const int k  = t + it * NTHREADS;
        const int i  = k / F4_PER_ROW;
        const int j4 = (k - i * F4_PER_ROW) * 4;
        float dot = m[it].x * s_arg[j4]
                  + m[it].y * s_arg[j4 + 1]
                  + m[it].z * s_arg[j4 + 2]
                  + m[it].w * s_arg[j4 + 3];
        acc = fmaf(s_ctx[i], dot, acc);
    }
    {   // masked last iteration
        const int k  = v9 ? k9 : 0;
        const int i  = k / F4_PER_ROW;
        const int j4 = (k - i * F4_PER_ROW) * 4;
        float dot = m[ITERS - 1].x * s_arg[j4]
                  + m[ITERS - 1].y * s_arg[j4 + 1]
                  + m[ITERS - 1].z * s_arg[j4 + 2]
                  + m[ITERS - 1].w * s_arg[j4 + 3];
        const float c = v9 ? s_ctx[i] : 0.0f;
        acc = fmaf(c, dot, acc);
    }

    // Warp reduction
    #pragma unroll
    for (int o = 16; o > 0; o >>= 1)
        acc += __shfl_xor_sync(0xFFFFFFFFu, acc, o);

    if ((t & 31) == 0)
        s_red[t >> 5] = acc;
    __syncthreads();

    if (t < (NTHREADS / 32)) {
        acc = s_red[t];
        #pragma unroll
        for (int o = (NTHREADS / 64); o > 0; o >>= 1)
            acc += __shfl_xor_sync(0xFFu, acc, o);
        if (t == 0)
            out[b] = acc;
    }
}

extern "C" void kernel_launch(void* const* d_in, const int* in_sizes, int n_in,
                              void* d_out, int out_size)
{
    const int*   X_argument    = (const int*)  d_in[0];
    const int*   X_functor     = (const int*)  d_in[1];
    const int*   X_context     = (const int*)  d_in[2];
    const float* noun_matrix   = (const float*)d_in[3];
    const float* functor_table = (const float*)d_in[4];
    const float* context_table = (const float*)d_in[5];
    float* out = (float*)d_out;

    matrix_skipgram_kernel<<<BATCH, NTHREADS>>>(
        X_argument, X_functor, X_context,
        noun_matrix, functor_table, context_table, out);
}